// round 16
// baseline (speedup 1.0000x reference)
#include <cuda_runtime.h>
#include <cuda_bf16.h>
#include <cuda_fp8.h>
#include <math.h>
#include <stdint.h>

// Problem constants
#define BB 128
#define SS 1024
#define HH 256
#define RR (BB*SS)
#define NEGV 1e9f
#define NSPLIT 16
#define SCHUNK (SS/NSPLIT)   // 64

// Scratch (device globals; no allocation allowed)
__device__ float g_scores[RR];
__device__ float g_e[RR];
__device__ float g_inv[BB];
__device__ float g_part[BB][NSPLIT][HH];
__device__ float g_qg[BB*HH];
__device__ float g_qp[BB*HH];
__device__ unsigned char g_w8[2][HH*HH];          // e4m3 wg, wp
__device__ unsigned char g_ref8[(size_t)RR*HH];   // e4m3 ref (32 MB), written by gemm1

__device__ __forceinline__ float fast_tanh(float x) {
    float y;
    asm("tanh.approx.f32 %0, %1;" : "=f"(y) : "f"(x));
    return y;
}
__device__ __forceinline__ unsigned smem_u32(const void* p) {
    return (unsigned)__cvta_generic_to_shared(p);
}
__device__ __forceinline__ float e4m3_f32(unsigned char x) {
    __half_raw h = __nv_cvt_fp8_to_halfraw(x, __NV_E4M3);
    return __half2float(*(__half*)&h);
}
#define CP_ASYNC16(dst, src) \
    asm volatile("cp.async.cg.shared.global [%0], [%1], 16;" :: "r"(dst), "l"(src))
#define CP_COMMIT() asm volatile("cp.async.commit_group;")
#define CP_WAIT0()  asm volatile("cp.async.wait_group 0;" ::: "memory")
#define CP_WAIT1()  asm volatile("cp.async.wait_group 1;" ::: "memory")

#define LDMX4(r0, r1, r2, r3, addr) \
    asm volatile("ldmatrix.sync.aligned.m8n8.x4.b16 {%0,%1,%2,%3}, [%4];" \
                 : "=r"(r0), "=r"(r1), "=r"(r2), "=r"(r3) : "r"(addr))

// Pack 4 consecutive floats (k order) into 4 e4m3 bytes (byte0 = first k).
__device__ __forceinline__ unsigned pack_e4m3x4(float f0, float f1, float f2, float f3) {
    unsigned short lo, hi;
    asm("cvt.rn.satfinite.e4m3x2.f32 %0, %1, %2;" : "=h"(lo) : "f"(f1), "f"(f0));
    asm("cvt.rn.satfinite.e4m3x2.f32 %0, %1, %2;" : "=h"(hi) : "f"(f3), "f"(f2));
    return (unsigned)lo | ((unsigned)hi << 16);
}

// ---------------------------------------------------------------------------
// Convert wg, wp to e4m3 once per launch.
// ---------------------------------------------------------------------------
__global__ void convert_w_kernel(const float* __restrict__ wg,
                                 const float* __restrict__ wp) {
    int i = blockIdx.x * blockDim.x + threadIdx.x;   // float4 index
    float4 a = ((const float4*)wg)[i];
    float4 b = ((const float4*)wp)[i];
    ((unsigned*)g_w8[0])[i] = pack_e4m3x4(a.x, a.y, a.z, a.w);
    ((unsigned*)g_w8[1])[i] = pack_e4m3x4(b.x, b.y, b.z, b.w);
}

// ---------------------------------------------------------------------------
// q[b,h] = sum_d in[b,d] * W[h,d]  (fp32, tiny).
// dst=0: in = query.  dst=1: in = glimpse computed inline from partials.
// ---------------------------------------------------------------------------
__global__ void qmat_kernel(const float* __restrict__ query,
                            const float* __restrict__ W, int dst) {
    int b = blockIdx.x;
    int tid = threadIdx.x;
    __shared__ float qs[HH];
    if (dst == 0) {
        qs[tid] = query[b * HH + tid];
    } else {
        float s = 0.f;
#pragma unroll
        for (int p = 0; p < NSPLIT; p++) s += g_part[b][p][tid];
        qs[tid] = s * g_inv[b] + query[b * HH + tid];
    }
    __syncthreads();

    int warp = tid >> 5, lane = tid & 31;
    float* outp = (dst ? g_qp : g_qg) + b * HH;
    int hbase = blockIdx.y * 64 + warp * 8;
#pragma unroll
    for (int hh = 0; hh < 8; hh++) {
        int h = hbase + hh;
        const float* wrow = W + h * HH;
        float s = 0.f;
#pragma unroll
        for (int i = 0; i < 8; i++) s += qs[lane + 32 * i] * wrow[lane + 32 * i];
#pragma unroll
        for (int o = 16; o; o >>= 1) s += __shfl_xor_sync(0xffffffffu, s, o);
        if (lane == 0) outp[h] = s;
    }
}

// ---------------------------------------------------------------------------
// Fused FP8 tensor-core GEMM + tanh + dot(v) reduce, 3-stage cp.async pipe.
// Tile BM=128 x BN=256 (all h), BK=64 bytes.  512 threads = 16 warps (4m x 4n).
// CONV=1: A from fp32 ref (LDG prefetch + pack), also STG'd to g_ref8.
// CONV=0: A via cp.async from g_ref8.
// ---------------------------------------------------------------------------
#define BM 128
#define BKB 64              // K bytes per chunk
#define NCH (HH/BKB)        // 4
#define WSTB 80             // smem byte stride per row (64 + 16 pad)
#define ST_A (BM*WSTB)      // 10240
#define ST_W (HH*WSTB)      // 20480
#define ST_BYTES (ST_A + ST_W)       // 30720
#define GEMM_DSMEM (3*ST_BYTES)      // 92160

extern __shared__ unsigned char dyn8[];

template<int CONV>
__global__ void __launch_bounds__(512, 1) gemm_tanh_mma(
    const float* __restrict__ ref,
    const float* __restrict__ bias, const float* __restrict__ v,
    const int* __restrict__ mask, float* __restrict__ out, int sel)
{
    __shared__ float red[BM][5];

    int tid = threadIdx.x;
    int warp = tid >> 5, lane = tid & 31;
    int wm = warp & 3, wn = warp >> 2;
    int gid = lane >> 2, quad = lane & 3;
    int rbase = blockIdx.x * BM;
    int b = rbase >> 10;

    const unsigned char* W8 = g_w8[sel];
    unsigned smem_base = smem_u32(dyn8);

    // A coords: 128 rows x 4 16B segs = 512 units, one per thread.
    int arow = tid >> 2, aseg = tid & 3;
    const unsigned char* A8 = g_ref8 + (size_t)rbase * HH;           // CONV=0 src
    const float* Af = ref + (size_t)(rbase + arow) * HH + aseg * 16; // CONV=1 src
    unsigned char* A8w = g_ref8 + (size_t)(rbase + arow) * HH + aseg * 16;

    float acc[2][8][4];
#pragma unroll
    for (int mt = 0; mt < 2; mt++)
#pragma unroll
        for (int nt = 0; nt < 8; nt++)
#pragma unroll
            for (int k = 0; k < 4; k++) acc[mt][nt][k] = 0.f;

    // ---- issue chunk (c) into stage (st): W always; A too when CONV=0 ----
    auto issue = [&](int c, int st) {
        unsigned abase = smem_base + st * ST_BYTES;
        unsigned wbase = abase + ST_A;
        if (!CONV) {
            CP_ASYNC16(abase + arow * WSTB + aseg * 16,
                       A8 + (size_t)arow * HH + c * BKB + aseg * 16);
        }
#pragma unroll
        for (int i = 0; i < 2; i++) {
            int u = tid + i * 512;               // 0..1023 (256 rows x 4 segs)
            int row = u >> 2, seg = u & 3;
            CP_ASYNC16(wbase + row * WSTB + seg * 16,
                       W8 + (size_t)row * HH + c * BKB + seg * 16);
        }
        CP_COMMIT();
    };

    float4 pre0, pre1, pre2, pre3;   // CONV prefetch
    if (CONV) {
        pre0 = *(const float4*)(Af);
        pre1 = *(const float4*)(Af + 4);
        pre2 = *(const float4*)(Af + 8);
        pre3 = *(const float4*)(Af + 12);
    }
    issue(0, 0);
    issue(1, 1);

    // ldmatrix lane coords
    int row16 = lane & 15, khalf = lane >> 4;       // A
    int g8 = lane >> 3, r8 = lane & 7;              // B

#pragma unroll
    for (int c = 0; c < NCH; c++) {
        int st = c % 3;
        unsigned abase = smem_base + st * ST_BYTES;
        unsigned wbase = abase + ST_A;

        if (c < NCH - 1) { CP_WAIT1(); } else { CP_WAIT0(); }
        if (CONV) {
            uint4 av;
            av.x = pack_e4m3x4(pre0.x, pre0.y, pre0.z, pre0.w);
            av.y = pack_e4m3x4(pre1.x, pre1.y, pre1.z, pre1.w);
            av.z = pack_e4m3x4(pre2.x, pre2.y, pre2.z, pre2.w);
            av.w = pack_e4m3x4(pre3.x, pre3.y, pre3.z, pre3.w);
            *(uint4*)(dyn8 + st * ST_BYTES + arow * WSTB + aseg * 16) = av;
            *(uint4*)(A8w + c * BKB) = av;
        }
        __syncthreads();
        if (c + 2 < NCH) issue(c + 2, (c + 2) % 3);
        if (CONV && c + 1 < NCH) {
            int kn = (c + 1) * BKB;
            pre0 = *(const float4*)(Af + kn);
            pre1 = *(const float4*)(Af + kn + 4);
            pre2 = *(const float4*)(Af + kn + 8);
            pre3 = *(const float4*)(Af + kn + 12);
        }

#pragma unroll
        for (int ks = 0; ks < 2; ks++) {
            unsigned a[2][4];
#pragma unroll
            for (int mt = 0; mt < 2; mt++) {
                unsigned addr = abase + (wm * 32 + mt * 16 + row16) * WSTB
                              + ks * 32 + khalf * 16;
                LDMX4(a[mt][0], a[mt][1], a[mt][2], a[mt][3], addr);
            }
            unsigned bfr[8][2];
#pragma unroll
            for (int ntp = 0; ntp < 4; ntp++) {
                int nrow = wn * 64 + ntp * 16 + ((g8 >> 1) & 1) * 8 + r8;
                unsigned addr = wbase + nrow * WSTB + ks * 32 + (g8 & 1) * 16;
                LDMX4(bfr[2*ntp][0], bfr[2*ntp][1],
                      bfr[2*ntp+1][0], bfr[2*ntp+1][1], addr);
            }
#pragma unroll
            for (int nt = 0; nt < 8; nt++) {
#pragma unroll
                for (int mt = 0; mt < 2; mt++) {
                    asm volatile(
                        "mma.sync.aligned.m16n8k32.row.col.f32.e4m3.e4m3.f32 "
                        "{%0,%1,%2,%3}, {%4,%5,%6,%7}, {%8,%9}, {%0,%1,%2,%3};"
                        : "+f"(acc[mt][nt][0]), "+f"(acc[mt][nt][1]),
                          "+f"(acc[mt][nt][2]), "+f"(acc[mt][nt][3])
                        : "r"(a[mt][0]), "r"(a[mt][1]), "r"(a[mt][2]), "r"(a[mt][3]),
                          "r"(bfr[nt][0]), "r"(bfr[nt][1]));
                }
            }
        }
    }

    // Epilogue: bias + q, tanh, dot v, reduce.
    const float* q = (sel ? g_qp : g_qg) + b * HH;
    float bq[8][2], vv[8][2];
#pragma unroll
    for (int nt = 0; nt < 8; nt++) {
        int col = wn * 64 + nt * 8 + quad * 2;
        bq[nt][0] = bias[col] + q[col];
        bq[nt][1] = bias[col + 1] + q[col + 1];
        vv[nt][0] = v[col];
        vv[nt][1] = v[col + 1];
    }

#pragma unroll
    for (int mt = 0; mt < 2; mt++) {
        float lo = 0.f, hi = 0.f;
#pragma unroll
        for (int nt = 0; nt < 8; nt++) {
            lo += fast_tanh(acc[mt][nt][0] + bq[nt][0]) * vv[nt][0];
            lo += fast_tanh(acc[mt][nt][1] + bq[nt][1]) * vv[nt][1];
            hi += fast_tanh(acc[mt][nt][2] + bq[nt][0]) * vv[nt][0];
            hi += fast_tanh(acc[mt][nt][3] + bq[nt][1]) * vv[nt][1];
        }
        lo += __shfl_xor_sync(0xffffffffu, lo, 1);
        lo += __shfl_xor_sync(0xffffffffu, lo, 2);
        hi += __shfl_xor_sync(0xffffffffu, hi, 1);
        hi += __shfl_xor_sync(0xffffffffu, hi, 2);
        if (quad == 0) {
            red[wm * 32 + mt * 16 + gid][wn]     = lo;
            red[wm * 32 + mt * 16 + gid + 8][wn] = hi;
        }
    }
    __syncthreads();

    if (tid < BM) {
        float t = red[tid][0] + red[tid][1] + red[tid][2] + red[tid][3];
        int r = rbase + tid;
        if (out) out[r] = t - (float)mask[r] * NEGV;
        else     g_scores[r] = t;
    }
}

// ---------------------------------------------------------------------------
// Softmax prep: per batch, masked max + exp + sum.
// ---------------------------------------------------------------------------
__global__ void softmax_prep_kernel(const int* __restrict__ mask) {
    int b = blockIdx.x;
    int tid = threadIdx.x;
    __shared__ float e[SS];
    __shared__ float red[256];

    float lm = -INFINITY;
#pragma unroll
    for (int i = 0; i < 4; i++) {
        int s = tid + i * 256;
        float val = g_scores[b * SS + s] - (float)mask[b * SS + s] * NEGV;
        e[s] = val;
        lm = fmaxf(lm, val);
    }
    red[tid] = lm;
    __syncthreads();
    for (int o = 128; o; o >>= 1) {
        if (tid < o) red[tid] = fmaxf(red[tid], red[tid + o]);
        __syncthreads();
    }
    float mx = red[0];
    __syncthreads();

    float ls = 0.f;
#pragma unroll
    for (int i = 0; i < 4; i++) {
        int s = tid + i * 256;
        float ev = expf(e[s] - mx);
        g_e[b * SS + s] = ev;
        ls += ev;
    }
    red[tid] = ls;
    __syncthreads();
    for (int o = 128; o; o >>= 1) {
        if (tid < o) red[tid] += red[tid + o];
        __syncthreads();
    }
    if (tid == 0) g_inv[b] = 1.0f / red[0];
}

// ---------------------------------------------------------------------------
// Glimpse partial from fp8 ref: grid (NSPLIT, BB).
// ---------------------------------------------------------------------------
__global__ void glimpse_partial_kernel() {
    int split = blockIdx.x, b = blockIdx.y;
    int tid = threadIdx.x;
    int s0 = split * SCHUNK;
    __shared__ float es[SCHUNK];
    if (tid < SCHUNK) es[tid] = g_e[b * SS + s0 + tid];
    __syncthreads();

    const unsigned char* rb = g_ref8 + ((size_t)b * SS + s0) * HH;
    int d = tid;
    float a0 = 0.f, a1 = 0.f, a2 = 0.f, a3 = 0.f;
#pragma unroll 4
    for (int s = 0; s < SCHUNK; s += 4) {
        a0 += es[s]     * e4m3_f32(rb[(size_t)(s)     * HH + d]);
        a1 += es[s + 1] * e4m3_f32(rb[(size_t)(s + 1) * HH + d]);
        a2 += es[s + 2] * e4m3_f32(rb[(size_t)(s + 2) * HH + d]);
        a3 += es[s + 3] * e4m3_f32(rb[(size_t)(s + 3) * HH + d]);
    }
    g_part[b][split][d] = (a0 + a1) + (a2 + a3);
}

// ---------------------------------------------------------------------------
// Launch. Input order: ref, query, mask, wg, bg, wqg, vg, wp, bp, wqp, vp
// ---------------------------------------------------------------------------
extern "C" void kernel_launch(void* const* d_in, const int* in_sizes, int n_in,
                              void* d_out, int out_size) {
    const float* ref   = (const float*)d_in[0];
    const float* query = (const float*)d_in[1];
    const int*   mask  = (const int*)  d_in[2];
    const float* wg    = (const float*)d_in[3];
    const float* bg    = (const float*)d_in[4];
    const float* wqg   = (const float*)d_in[5];
    const float* vg    = (const float*)d_in[6];
    const float* wp    = (const float*)d_in[7];
    const float* bp    = (const float*)d_in[8];
    const float* wqp   = (const float*)d_in[9];
    const float* vp    = (const float*)d_in[10];
    float* out = (float*)d_out;

    cudaFuncSetAttribute(gemm_tanh_mma<1>,
                         cudaFuncAttributeMaxDynamicSharedMemorySize,
                         GEMM_DSMEM);
    cudaFuncSetAttribute(gemm_tanh_mma<0>,
                         cudaFuncAttributeMaxDynamicSharedMemorySize,
                         GEMM_DSMEM);

    convert_w_kernel<<<64, 256>>>(wg, wp);
    qmat_kernel<<<dim3(BB, 4), 256>>>(query, wqg, 0);
    // gemm1: fp32 A path, converts + persists fp8 ref for downstream
    gemm_tanh_mma<1><<<RR / BM, 512, GEMM_DSMEM>>>(ref, bg, vg, mask, nullptr, 0);
    softmax_prep_kernel<<<BB, 256>>>(mask);
    glimpse_partial_kernel<<<dim3(NSPLIT, BB), 256>>>();
    // qmat dst=1 computes glimpse (combine) inline
    qmat_kernel<<<dim3(BB, 4), 256>>>(query, wqp, 1);
    // gemm2: fp8 A via cp.async
    gemm_tanh_mma<0><<<RR / BM, 512, GEMM_DSMEM>>>(ref, bp, vp, mask, out, 1);
}

// round 17
// speedup vs baseline: 1.0734x; 1.0734x over previous
#include <cuda_runtime.h>
#include <cuda_bf16.h>
#include <cuda_fp8.h>
#include <math.h>
#include <stdint.h>

// Problem constants
#define BB 128
#define SS 1024
#define HH 256
#define RR (BB*SS)
#define NEGV 1e9f
#define NSPLIT 16
#define SCHUNK (SS/NSPLIT)   // 64

// Scratch (device globals; no allocation allowed)
__device__ float g_e[RR];                         // exp(masked score), from gemm1
__device__ float g_inv[BB];
__device__ float g_part[BB][NSPLIT][HH];
__device__ float g_qg[BB*HH];
__device__ float g_qp[BB*HH];
__device__ unsigned char g_w8[2][HH*HH];          // e4m3 wg, wp
__device__ unsigned char g_ref8[(size_t)RR*HH];   // e4m3 ref (32 MB), written by gemm1

__device__ __forceinline__ float fast_tanh(float x) {
    float y;
    asm("tanh.approx.f32 %0, %1;" : "=f"(y) : "f"(x));
    return y;
}
__device__ __forceinline__ unsigned smem_u32(const void* p) {
    return (unsigned)__cvta_generic_to_shared(p);
}
__device__ __forceinline__ float e4m3_f32(unsigned char x) {
    __half_raw h = __nv_cvt_fp8_to_halfraw(x, __NV_E4M3);
    return __half2float(*(__half*)&h);
}
#define CP_ASYNC16(dst, src) \
    asm volatile("cp.async.cg.shared.global [%0], [%1], 16;" :: "r"(dst), "l"(src))
#define CP_COMMIT() asm volatile("cp.async.commit_group;")
#define CP_WAIT0()  asm volatile("cp.async.wait_group 0;" ::: "memory")
#define CP_WAIT1()  asm volatile("cp.async.wait_group 1;" ::: "memory")

#define LDMX4(r0, r1, r2, r3, addr) \
    asm volatile("ldmatrix.sync.aligned.m8n8.x4.b16 {%0,%1,%2,%3}, [%4];" \
                 : "=r"(r0), "=r"(r1), "=r"(r2), "=r"(r3) : "r"(addr))

// Pack 4 consecutive floats (k order) into 4 e4m3 bytes (byte0 = first k).
__device__ __forceinline__ unsigned pack_e4m3x4(float f0, float f1, float f2, float f3) {
    unsigned short lo, hi;
    asm("cvt.rn.satfinite.e4m3x2.f32 %0, %1, %2;" : "=h"(lo) : "f"(f1), "f"(f0));
    asm("cvt.rn.satfinite.e4m3x2.f32 %0, %1, %2;" : "=h"(hi) : "f"(f3), "f"(f2));
    return (unsigned)lo | ((unsigned)hi << 16);
}

// ---------------------------------------------------------------------------
// Convert wg, wp to e4m3 once per launch.
// ---------------------------------------------------------------------------
__global__ void convert_w_kernel(const float* __restrict__ wg,
                                 const float* __restrict__ wp) {
    int i = blockIdx.x * blockDim.x + threadIdx.x;   // float4 index
    float4 a = ((const float4*)wg)[i];
    float4 b = ((const float4*)wp)[i];
    ((unsigned*)g_w8[0])[i] = pack_e4m3x4(a.x, a.y, a.z, a.w);
    ((unsigned*)g_w8[1])[i] = pack_e4m3x4(b.x, b.y, b.z, b.w);
}

// ---------------------------------------------------------------------------
// q[b,h] = sum_d in[b,d] * W[h,d]  (fp32, tiny).
// dst=0: in = query.  dst=1: in = glimpse computed inline from partials.
// ---------------------------------------------------------------------------
__global__ void qmat_kernel(const float* __restrict__ query,
                            const float* __restrict__ W, int dst) {
    int b = blockIdx.x;
    int tid = threadIdx.x;
    __shared__ float qs[HH];
    if (dst == 0) {
        qs[tid] = query[b * HH + tid];
    } else {
        float s = 0.f;
#pragma unroll
        for (int p = 0; p < NSPLIT; p++) s += g_part[b][p][tid];
        qs[tid] = s * g_inv[b] + query[b * HH + tid];
    }
    __syncthreads();

    int warp = tid >> 5, lane = tid & 31;
    float* outp = (dst ? g_qp : g_qg) + b * HH;
    int hbase = blockIdx.y * 64 + warp * 8;
#pragma unroll
    for (int hh = 0; hh < 8; hh++) {
        int h = hbase + hh;
        const float* wrow = W + h * HH;
        float s = 0.f;
#pragma unroll
        for (int i = 0; i < 8; i++) s += qs[lane + 32 * i] * wrow[lane + 32 * i];
#pragma unroll
        for (int o = 16; o; o >>= 1) s += __shfl_xor_sync(0xffffffffu, s, o);
        if (lane == 0) outp[h] = s;
    }
}

// ---------------------------------------------------------------------------
// Fused FP8 tensor-core GEMM + tanh + dot(v) reduce, 3-stage cp.async pipe.
// Tile BM=64 x BN=256 (all h), BK=64 bytes.  256 threads = 8 warps (2m x 4n).
// CONV=1: A from fp32 ref (LDG prefetch + pack), also STG'd to g_ref8;
//         epilogue writes g_e = exp(score - mask*NEG)  (no-max softmax).
// CONV=0: A via cp.async from g_ref8; epilogue writes out = score - mask*NEG.
// ---------------------------------------------------------------------------
#define BM 64
#define BKB 64              // K bytes per chunk
#define NCH (HH/BKB)        // 4
#define WSTB 80             // smem byte stride per row (64 + 16 pad)
#define ST_A (BM*WSTB)      // 5120
#define ST_W (HH*WSTB)      // 20480
#define ST_BYTES (ST_A + ST_W)       // 25600
#define GEMM_DSMEM (3*ST_BYTES)      // 76800

extern __shared__ unsigned char dyn8[];

template<int CONV>
__global__ void __launch_bounds__(256, 2) gemm_tanh_mma(
    const float* __restrict__ ref,
    const float* __restrict__ bias, const float* __restrict__ v,
    const int* __restrict__ mask, float* __restrict__ out, int sel)
{
    __shared__ float red[64][5];

    int tid = threadIdx.x;
    int warp = tid >> 5, lane = tid & 31;
    int wm = warp & 1, wn = warp >> 1;
    int gid = lane >> 2, quad = lane & 3;
    int rbase = blockIdx.x * BM;
    int b = rbase >> 10;

    const unsigned char* W8 = g_w8[sel];
    unsigned smem_base = smem_u32(dyn8);

    // A coords: 64 rows x 4 16B segs, one uint4 per thread per chunk.
    int arow = tid >> 2, aseg = tid & 3;
    const unsigned char* A8 = g_ref8 + (size_t)rbase * HH;           // CONV=0 src
    const float* Af = ref + (size_t)(rbase + arow) * HH + aseg * 16; // CONV=1 src
    unsigned char* A8w = g_ref8 + (size_t)(rbase + arow) * HH + aseg * 16;

    float acc[2][8][4];
#pragma unroll
    for (int mt = 0; mt < 2; mt++)
#pragma unroll
        for (int nt = 0; nt < 8; nt++)
#pragma unroll
            for (int k = 0; k < 4; k++) acc[mt][nt][k] = 0.f;

    // ---- issue chunk (c) into stage (st): W always; A too when CONV=0 ----
    auto issue = [&](int c, int st) {
        unsigned abase = smem_base + st * ST_BYTES;
        unsigned wbase = abase + ST_A;
        if (!CONV) {
            CP_ASYNC16(abase + arow * WSTB + aseg * 16,
                       A8 + (size_t)arow * HH + c * BKB + aseg * 16);
        }
#pragma unroll
        for (int i = 0; i < 4; i++) {
            int u = tid + i * 256;
            int row = u >> 2, seg = u & 3;
            CP_ASYNC16(wbase + row * WSTB + seg * 16,
                       W8 + (size_t)row * HH + c * BKB + seg * 16);
        }
        CP_COMMIT();
    };

    float4 pre0, pre1, pre2, pre3;   // CONV prefetch (chunk c)
    if (CONV) {
        pre0 = *(const float4*)(Af);
        pre1 = *(const float4*)(Af + 4);
        pre2 = *(const float4*)(Af + 8);
        pre3 = *(const float4*)(Af + 12);
    }
    issue(0, 0);
    issue(1, 1);

    // ldmatrix lane coords
    int row16 = lane & 15, khalf = lane >> 4;       // A
    int g8 = lane >> 3, r8 = lane & 7;              // B

#pragma unroll
    for (int c = 0; c < NCH; c++) {
        int st = c % 3;
        unsigned abase = smem_base + st * ST_BYTES;
        unsigned wbase = abase + ST_A;

        if (c < NCH - 1) { CP_WAIT1(); } else { CP_WAIT0(); }
        if (CONV) {
            uint4 av;
            av.x = pack_e4m3x4(pre0.x, pre0.y, pre0.z, pre0.w);
            av.y = pack_e4m3x4(pre1.x, pre1.y, pre1.z, pre1.w);
            av.z = pack_e4m3x4(pre2.x, pre2.y, pre2.z, pre2.w);
            av.w = pack_e4m3x4(pre3.x, pre3.y, pre3.z, pre3.w);
            *(uint4*)(dyn8 + st * ST_BYTES + arow * WSTB + aseg * 16) = av;
            *(uint4*)(A8w + c * BKB) = av;
        }
        __syncthreads();
        if (c + 2 < NCH) issue(c + 2, (c + 2) % 3);
        if (CONV && c + 1 < NCH) {
            int kn = (c + 1) * BKB;
            pre0 = *(const float4*)(Af + kn);
            pre1 = *(const float4*)(Af + kn + 4);
            pre2 = *(const float4*)(Af + kn + 8);
            pre3 = *(const float4*)(Af + kn + 12);
        }

#pragma unroll
        for (int ks = 0; ks < 2; ks++) {
            unsigned a[2][4];
#pragma unroll
            for (int mt = 0; mt < 2; mt++) {
                unsigned addr = abase + (wm * 32 + mt * 16 + row16) * WSTB
                              + ks * 32 + khalf * 16;
                LDMX4(a[mt][0], a[mt][1], a[mt][2], a[mt][3], addr);
            }
            unsigned bfr[8][2];
#pragma unroll
            for (int ntp = 0; ntp < 4; ntp++) {
                int nrow = wn * 64 + ntp * 16 + ((g8 >> 1) & 1) * 8 + r8;
                unsigned addr = wbase + nrow * WSTB + ks * 32 + (g8 & 1) * 16;
                LDMX4(bfr[2*ntp][0], bfr[2*ntp][1],
                      bfr[2*ntp+1][0], bfr[2*ntp+1][1], addr);
            }
#pragma unroll
            for (int nt = 0; nt < 8; nt++) {
#pragma unroll
                for (int mt = 0; mt < 2; mt++) {
                    asm volatile(
                        "mma.sync.aligned.m16n8k32.row.col.f32.e4m3.e4m3.f32 "
                        "{%0,%1,%2,%3}, {%4,%5,%6,%7}, {%8,%9}, {%0,%1,%2,%3};"
                        : "+f"(acc[mt][nt][0]), "+f"(acc[mt][nt][1]),
                          "+f"(acc[mt][nt][2]), "+f"(acc[mt][nt][3])
                        : "r"(a[mt][0]), "r"(a[mt][1]), "r"(a[mt][2]), "r"(a[mt][3]),
                          "r"(bfr[nt][0]), "r"(bfr[nt][1]));
                }
            }
        }
    }

    // Epilogue: bias + q, tanh, dot v, reduce.
    const float* q = (sel ? g_qp : g_qg) + b * HH;
    float bq[8][2], vv[8][2];
#pragma unroll
    for (int nt = 0; nt < 8; nt++) {
        int col = wn * 64 + nt * 8 + quad * 2;
        bq[nt][0] = bias[col] + q[col];
        bq[nt][1] = bias[col + 1] + q[col + 1];
        vv[nt][0] = v[col];
        vv[nt][1] = v[col + 1];
    }

#pragma unroll
    for (int mt = 0; mt < 2; mt++) {
        float lo = 0.f, hi = 0.f;
#pragma unroll
        for (int nt = 0; nt < 8; nt++) {
            lo += fast_tanh(acc[mt][nt][0] + bq[nt][0]) * vv[nt][0];
            lo += fast_tanh(acc[mt][nt][1] + bq[nt][1]) * vv[nt][1];
            hi += fast_tanh(acc[mt][nt][2] + bq[nt][0]) * vv[nt][0];
            hi += fast_tanh(acc[mt][nt][3] + bq[nt][1]) * vv[nt][1];
        }
        lo += __shfl_xor_sync(0xffffffffu, lo, 1);
        lo += __shfl_xor_sync(0xffffffffu, lo, 2);
        hi += __shfl_xor_sync(0xffffffffu, hi, 1);
        hi += __shfl_xor_sync(0xffffffffu, hi, 2);
        if (quad == 0) {
            red[wm * 32 + mt * 16 + gid][wn]     = lo;
            red[wm * 32 + mt * 16 + gid + 8][wn] = hi;
        }
    }
    __syncthreads();

    if (tid < 64) {
        float t = red[tid][0] + red[tid][1] + red[tid][2] + red[tid][3];
        int r = rbase + tid;
        float masked = t - (float)mask[r] * NEGV;
        if (CONV) g_e[r] = expf(masked);     // softmax numerator (no-max form)
        else      out[r] = masked;
    }
}

// ---------------------------------------------------------------------------
// Per-batch sum of e -> inv.  One block per batch.
// ---------------------------------------------------------------------------
__global__ void softmax_sum_kernel() {
    int b = blockIdx.x;
    int tid = threadIdx.x;
    __shared__ float red[256];
    float ls = 0.f;
#pragma unroll
    for (int i = 0; i < 4; i++) ls += g_e[b * SS + tid + i * 256];
    red[tid] = ls;
    __syncthreads();
    for (int o = 128; o; o >>= 1) {
        if (tid < o) red[tid] += red[tid + o];
        __syncthreads();
    }
    if (tid == 0) g_inv[b] = 1.0f / red[0];
}

// ---------------------------------------------------------------------------
// Glimpse partial from fp8 ref: grid (NSPLIT, BB).
// ---------------------------------------------------------------------------
__global__ void glimpse_partial_kernel() {
    int split = blockIdx.x, b = blockIdx.y;
    int tid = threadIdx.x;
    int s0 = split * SCHUNK;
    __shared__ float es[SCHUNK];
    if (tid < SCHUNK) es[tid] = g_e[b * SS + s0 + tid];
    __syncthreads();

    const unsigned char* rb = g_ref8 + ((size_t)b * SS + s0) * HH;
    int d = tid;
    float a0 = 0.f, a1 = 0.f, a2 = 0.f, a3 = 0.f;
#pragma unroll 4
    for (int s = 0; s < SCHUNK; s += 4) {
        a0 += es[s]     * e4m3_f32(rb[(size_t)(s)     * HH + d]);
        a1 += es[s + 1] * e4m3_f32(rb[(size_t)(s + 1) * HH + d]);
        a2 += es[s + 2] * e4m3_f32(rb[(size_t)(s + 2) * HH + d]);
        a3 += es[s + 3] * e4m3_f32(rb[(size_t)(s + 3) * HH + d]);
    }
    g_part[b][split][d] = (a0 + a1) + (a2 + a3);
}

// ---------------------------------------------------------------------------
// Launch. Input order: ref, query, mask, wg, bg, wqg, vg, wp, bp, wqp, vp
// ---------------------------------------------------------------------------
extern "C" void kernel_launch(void* const* d_in, const int* in_sizes, int n_in,
                              void* d_out, int out_size) {
    const float* ref   = (const float*)d_in[0];
    const float* query = (const float*)d_in[1];
    const int*   mask  = (const int*)  d_in[2];
    const float* wg    = (const float*)d_in[3];
    const float* bg    = (const float*)d_in[4];
    const float* wqg   = (const float*)d_in[5];
    const float* vg    = (const float*)d_in[6];
    const float* wp    = (const float*)d_in[7];
    const float* bp    = (const float*)d_in[8];
    const float* wqp   = (const float*)d_in[9];
    const float* vp    = (const float*)d_in[10];
    float* out = (float*)d_out;

    cudaFuncSetAttribute(gemm_tanh_mma<1>,
                         cudaFuncAttributeMaxDynamicSharedMemorySize,
                         GEMM_DSMEM);
    cudaFuncSetAttribute(gemm_tanh_mma<0>,
                         cudaFuncAttributeMaxDynamicSharedMemorySize,
                         GEMM_DSMEM);

    convert_w_kernel<<<64, 256>>>(wg, wp);
    qmat_kernel<<<dim3(BB, 4), 256>>>(query, wqg, 0);
    // gemm1: fp32 A path, converts + persists fp8 ref, writes e = exp(score)
    gemm_tanh_mma<1><<<RR / BM, 256, GEMM_DSMEM>>>(ref, bg, vg, mask, nullptr, 0);
    softmax_sum_kernel<<<BB, 256>>>();
    glimpse_partial_kernel<<<dim3(NSPLIT, BB), 256>>>();
    // qmat dst=1 computes glimpse (combine) inline
    qmat_kernel<<<dim3(BB, 4), 256>>>(query, wqp, 1);
    // gemm2: fp8 A via cp.async
    gemm_tanh_mma<0><<<RR / BM, 256, GEMM_DSMEM>>>(ref, bp, vp, mask, out, 1);
}